// round 7
// baseline (speedup 1.0000x reference)
#include <cuda_runtime.h>
#include <cuda_bf16.h>
#include <cstdint>

#define PRIME1 2654435761u
#define PRIME2 805459861u
#define HMASK  0x7FFFFu

#define TPB 256
#define PITCH 36   // mult of 4 (aligned float4 ops); 8-thread LDS.128 phases conflict-free

// Issue all 8 corner gathers for one level. x-adjacent corner pairs are
// CONSECUTIVE table entries (dense: always; hashed: when ix even, since
// ix+1 = ix^1 and xor/mask preserve the LSB flip -> pair {2k,2k+1}).
// An even pair start is one 16B-aligned LDG.128: 1 wavefront + 1 sector
// instead of 2 each.
template<int LVL>
__device__ __forceinline__ void issue_level(
    float x, float y, float z,
    const float2* __restrict__ emb, const float2* __restrict__ tab,
    float& fx, float& fy, float& fz, float2* dst)
{
    const float scale = (float)(16 << LVL) - 1.0f;
    const float px = fmaf(x, scale, 0.5f);
    const float py = fmaf(y, scale, 0.5f);
    const float pz = fmaf(z, scale, 0.5f);
    const float fxf = floorf(px), fyf = floorf(py), fzf = floorf(pz);
    fx = px - fxf; fy = py - fyf; fz = pz - fzf;
    const unsigned ix = (unsigned)fxf, iy = (unsigned)fyf, iz = (unsigned)fzf;

    if (LVL <= 2) {
        const unsigned s  = (LVL == 0) ? 17u : (LVL == 1) ? 33u : 65u;
        const unsigned s2 = s * s;
        const unsigned off = (LVL == 2) ? 35944u : 0u;
        const float2* base = (LVL == 0) ? emb : tab;
        const unsigned id = ix + iy * s + iz * s2 + off;
        const unsigned starts[4] = {id, id + s, id + s2, id + s2 + s};
        #pragma unroll
        for (int p = 0; p < 4; p++) {
            const unsigned j = starts[p];
            if (!(j & 1u)) {
                const float4 v = __ldg((const float4*)(base + j));
                dst[2*p]   = make_float2(v.x, v.y);
                dst[2*p+1] = make_float2(v.z, v.w);
            } else {
                dst[2*p]   = __ldg(base + j);
                dst[2*p+1] = __ldg(base + j + 1);
            }
        }
    } else {
        const unsigned off = 310576u + (unsigned)(LVL - 3) * 524288u;
        const unsigned hy0 = iy * PRIME1, hy1 = hy0 + PRIME1;
        const unsigned hz0 = iz * PRIME2, hz1 = hz0 + PRIME2;
        const unsigned hh[4] = {hy0 ^ hz0, hy1 ^ hz0, hy0 ^ hz1, hy1 ^ hz1};
        if (!(ix & 1u)) {
            #pragma unroll
            for (int p = 0; p < 4; p++) {
                const unsigned j0 = (ix ^ hh[p]) & HMASK;
                const float4 v = __ldcg((const float4*)(tab + ((j0 & ~1u) + off)));
                const bool first = !(j0 & 1u);
                dst[2*p].x   = first ? v.x : v.z;
                dst[2*p].y   = first ? v.y : v.w;
                dst[2*p+1].x = first ? v.z : v.x;
                dst[2*p+1].y = first ? v.w : v.y;
            }
        } else {
            #pragma unroll
            for (int p = 0; p < 4; p++) {
                dst[2*p]   = __ldcg(tab + (((ix      ) ^ hh[p]) & HMASK) + off);
                dst[2*p+1] = __ldcg(tab + (((ix + 1u) ^ hh[p]) & HMASK) + off);
            }
        }
    }
}

__global__ void __launch_bounds__(TPB, 6)
grid_encode_kernel(const float* __restrict__ inp,
                   const float2* __restrict__ emb,    // level 0 (4920 rows)
                   const float2* __restrict__ tab,    // levels 1..15
                   const int* __restrict__ boundp,
                   float* __restrict__ out,
                   int B)
{
    __shared__ float s_out[TPB * PITCH];

    const int tid = threadIdx.x;
    const int b = blockIdx.x * TPB + tid;        // < 2^21: fits int
    const bool valid = (b < B);

    float bnd = 1.0f;
    if (boundp) {
        int raw = __ldg(boundp);
        bnd = (raw > 0 && raw < 0x00800000) ? (float)raw : __int_as_float(raw);
    }
    const float inv = 0.5f / bnd;

    float x = 0.f, y = 0.f, z = 0.f;
    if (valid) {
        const float* p = inp + b * 3;
        x = __ldcs(p + 0); y = __ldcs(p + 1); z = __ldcs(p + 2);
    }
    x = fmaf(x, inv, 0.5f);
    y = fmaf(y, inv, 0.5f);
    z = fmaf(z, inv, 0.5f);

    if (valid) {
        // 2-stage software pipeline (level l+1 issued before level l consumed)
        // + results held in regs per level-PAIR so SMEM staging uses STS.128
        // (8 per point instead of 16 STS.64).
        float cfx, cfy, cfz;
        float2 cur[8];
        float keep0, keep1;   // even level's result, flushed with odd level's
        issue_level<0>(x, y, z, emb, tab, cfx, cfy, cfz, cur);

        #define CONSUME(L)                                                         \
        {                                                                          \
            const float gx = 1.0f - cfx, gy = 1.0f - cfy, gz = 1.0f - cfz;         \
            const float w00 = gx * gy, w10 = cfx * gy, w01 = gx * cfy, w11 = cfx * cfy; \
            const float wa = w00 * gz, wb = w10 * gz, wc = w01 * gz, wd = w11 * gz;\
            const float we = w00 * cfz, wf = w10 * cfz, wg = w01 * cfz, wh = w11 * cfz; \
            float r0 = wa * cur[0].x,          r1 = wa * cur[0].y;                 \
            r0 = fmaf(wb, cur[1].x, r0);       r1 = fmaf(wb, cur[1].y, r1);        \
            r0 = fmaf(wc, cur[2].x, r0);       r1 = fmaf(wc, cur[2].y, r1);        \
            r0 = fmaf(wd, cur[3].x, r0);       r1 = fmaf(wd, cur[3].y, r1);        \
            r0 = fmaf(we, cur[4].x, r0);       r1 = fmaf(we, cur[4].y, r1);        \
            r0 = fmaf(wf, cur[5].x, r0);       r1 = fmaf(wf, cur[5].y, r1);        \
            r0 = fmaf(wg, cur[6].x, r0);       r1 = fmaf(wg, cur[6].y, r1);        \
            r0 = fmaf(wh, cur[7].x, r0);       r1 = fmaf(wh, cur[7].y, r1);        \
            if (((L) & 1) == 0) {                                                  \
                keep0 = r0; keep1 = r1;                                            \
            } else {                                                               \
                *(float4*)&s_out[tid * PITCH + 2 * ((L) - 1)] =                    \
                    make_float4(keep0, keep1, r0, r1);                             \
            }                                                                      \
        }

        #define STEP(L)                                                            \
        {                                                                          \
            float nfx, nfy, nfz;                                                   \
            float2 nxt[8];                                                         \
            issue_level<(L) + 1>(x, y, z, emb, tab, nfx, nfy, nfz, nxt);           \
            CONSUME(L)                                                             \
            cfx = nfx; cfy = nfy; cfz = nfz;                                       \
            _Pragma("unroll")                                                      \
            for (int c = 0; c < 8; c++) cur[c] = nxt[c];                           \
        }

        STEP(0)  STEP(1)  STEP(2)  STEP(3)
        STEP(4)  STEP(5)  STEP(6)  STEP(7)
        STEP(8)  STEP(9)  STEP(10) STEP(11)
        STEP(12) STEP(13) STEP(14)
        CONSUME(15)

        #undef STEP
        #undef CONSUME
    }

    __syncthreads();

    // Coalesced float4 writeback, evict-first so the 256MB output stream
    // doesn't flush the 57MB table out of L2.
    const int blockBase = blockIdx.x * (TPB * 32);   // < 2^26*? 8192*8192=67M: fits
#pragma unroll
    for (int j = 0; j < 8; j++) {
        const int f4 = tid + j * TPB;
        const int fl = f4 * 4;
        const int p  = fl >> 5;
        const int k  = fl & 31;
        const int gp = blockIdx.x * TPB + p;
        if (gp < B) {
            const float4 v = *(const float4*)&s_out[p * PITCH + k];
            __stcs((float4*)&out[blockBase + fl], v);
        }
    }
}

extern "C" void kernel_launch(void* const* d_in, const int* in_sizes, int n_in,
                              void* d_out, int out_size)
{
    const float*  inp = (const float*)d_in[0];
    const float2* emb = (const float2*)d_in[1];
    const float2* tab = (const float2*)d_in[2];
    const int*    bnd = (n_in >= 4) ? (const int*)d_in[3] : nullptr;
    float* out = (float*)d_out;

    const int B = in_sizes[0] / 3;
    const int grid = (B + TPB - 1) / TPB;
    grid_encode_kernel<<<grid, TPB>>>(inp, emb, tab, bnd, out, B);
}

// round 10
// speedup vs baseline: 2.2645x; 2.2645x over previous
#include <cuda_runtime.h>
#include <cuda_bf16.h>
#include <cstdint>

#define PRIME1 2654435761u
#define PRIME2 805459861u
#define HMASK  0x7FFFFu

#define TPB 256
#define PITCH 36   // mult of 4 (aligned float4 ops); 8-thread LDS.128 phases conflict-free

// Issue all 8 corner gathers for one level. x-adjacent corner pairs are
// CONSECUTIVE table entries (dense: always; hashed: when ix even, since
// ix+1 = ix^1 and xor/mask preserve the LSB flip -> pair {2k,2k+1}).
// An even pair start is one 16B-aligned LDG.128: 1 wavefront + 1 sector
// instead of 2 each.
template<int LVL>
__device__ __forceinline__ void issue_level(
    float x, float y, float z,
    const float2* __restrict__ emb, const float2* __restrict__ tab,
    float& fx, float& fy, float& fz, float2* dst)
{
    const float scale = (float)(16 << LVL) - 1.0f;
    const float px = fmaf(x, scale, 0.5f);
    const float py = fmaf(y, scale, 0.5f);
    const float pz = fmaf(z, scale, 0.5f);
    const float fxf = floorf(px), fyf = floorf(py), fzf = floorf(pz);
    fx = px - fxf; fy = py - fyf; fz = pz - fzf;
    const unsigned ix = (unsigned)fxf, iy = (unsigned)fyf, iz = (unsigned)fzf;

    if (LVL <= 2) {
        const unsigned s  = (LVL == 0) ? 17u : (LVL == 1) ? 33u : 65u;
        const unsigned s2 = s * s;
        const unsigned off = (LVL == 2) ? 35944u : 0u;
        const float2* base = (LVL == 0) ? emb : tab;
        const unsigned id = ix + iy * s + iz * s2 + off;
        const unsigned starts[4] = {id, id + s, id + s2, id + s2 + s};
        #pragma unroll
        for (int p = 0; p < 4; p++) {
            const unsigned j = starts[p];
            if (!(j & 1u)) {
                const float4 v = __ldg((const float4*)(base + j));
                dst[2*p]   = make_float2(v.x, v.y);
                dst[2*p+1] = make_float2(v.z, v.w);
            } else {
                dst[2*p]   = __ldg(base + j);
                dst[2*p+1] = __ldg(base + j + 1);
            }
        }
    } else {
        const unsigned off = 310576u + (unsigned)(LVL - 3) * 524288u;
        const unsigned hy0 = iy * PRIME1, hy1 = hy0 + PRIME1;
        const unsigned hz0 = iz * PRIME2, hz1 = hz0 + PRIME2;
        const unsigned hh[4] = {hy0 ^ hz0, hy1 ^ hz0, hy0 ^ hz1, hy1 ^ hz1};
        if (!(ix & 1u)) {
            #pragma unroll
            for (int p = 0; p < 4; p++) {
                const unsigned j0 = (ix ^ hh[p]) & HMASK;
                const float4 v = __ldcg((const float4*)(tab + ((j0 & ~1u) + off)));
                const bool first = !(j0 & 1u);
                dst[2*p].x   = first ? v.x : v.z;
                dst[2*p].y   = first ? v.y : v.w;
                dst[2*p+1].x = first ? v.z : v.x;
                dst[2*p+1].y = first ? v.w : v.y;
            }
        } else {
            #pragma unroll
            for (int p = 0; p < 4; p++) {
                dst[2*p]   = __ldcg(tab + (((ix      ) ^ hh[p]) & HMASK) + off);
                dst[2*p+1] = __ldcg(tab + (((ix + 1u) ^ hh[p]) & HMASK) + off);
            }
        }
    }
}

__global__ void __launch_bounds__(TPB, 5)
grid_encode_kernel(const float* __restrict__ inp,
                   const float2* __restrict__ emb,    // level 0 (4920 rows)
                   const float2* __restrict__ tab,    // levels 1..15
                   const int* __restrict__ boundp,
                   float* __restrict__ out,
                   int B)
{
    __shared__ float s_out[TPB * PITCH];

    const int tid = threadIdx.x;
    const int b = blockIdx.x * TPB + tid;        // < 2^21: fits int
    const bool valid = (b < B);

    float bnd = 1.0f;
    if (boundp) {
        int raw = __ldg(boundp);
        bnd = (raw > 0 && raw < 0x00800000) ? (float)raw : __int_as_float(raw);
    }
    const float inv = 0.5f / bnd;

    float x = 0.f, y = 0.f, z = 0.f;
    if (valid) {
        const float* p = inp + b * 3;
        x = __ldcs(p + 0); y = __ldcs(p + 1); z = __ldcs(p + 2);
    }
    x = fmaf(x, inv, 0.5f);
    y = fmaf(y, inv, 0.5f);
    z = fmaf(z, inv, 0.5f);

    if (valid) {
        // 2-stage software pipeline (level l+1 issued before level l consumed)
        // + results held in regs per level-PAIR so SMEM staging uses STS.128
        // (8 per point instead of 16 STS.64).
        float cfx, cfy, cfz;
        float2 cur[8];
        float keep0, keep1;   // even level's result, flushed with odd level's
        issue_level<0>(x, y, z, emb, tab, cfx, cfy, cfz, cur);

        #define CONSUME(L)                                                         \
        {                                                                          \
            const float gx = 1.0f - cfx, gy = 1.0f - cfy, gz = 1.0f - cfz;         \
            const float w00 = gx * gy, w10 = cfx * gy, w01 = gx * cfy, w11 = cfx * cfy; \
            const float wa = w00 * gz, wb = w10 * gz, wc = w01 * gz, wd = w11 * gz;\
            const float we = w00 * cfz, wf = w10 * cfz, wg = w01 * cfz, wh = w11 * cfz; \
            float r0 = wa * cur[0].x,          r1 = wa * cur[0].y;                 \
            r0 = fmaf(wb, cur[1].x, r0);       r1 = fmaf(wb, cur[1].y, r1);        \
            r0 = fmaf(wc, cur[2].x, r0);       r1 = fmaf(wc, cur[2].y, r1);        \
            r0 = fmaf(wd, cur[3].x, r0);       r1 = fmaf(wd, cur[3].y, r1);        \
            r0 = fmaf(we, cur[4].x, r0);       r1 = fmaf(we, cur[4].y, r1);        \
            r0 = fmaf(wf, cur[5].x, r0);       r1 = fmaf(wf, cur[5].y, r1);        \
            r0 = fmaf(wg, cur[6].x, r0);       r1 = fmaf(wg, cur[6].y, r1);        \
            r0 = fmaf(wh, cur[7].x, r0);       r1 = fmaf(wh, cur[7].y, r1);        \
            if (((L) & 1) == 0) {                                                  \
                keep0 = r0; keep1 = r1;                                            \
            } else {                                                               \
                *(float4*)&s_out[tid * PITCH + 2 * ((L) - 1)] =                    \
                    make_float4(keep0, keep1, r0, r1);                             \
            }                                                                      \
        }

        #define STEP(L)                                                            \
        {                                                                          \
            float nfx, nfy, nfz;                                                   \
            float2 nxt[8];                                                         \
            issue_level<(L) + 1>(x, y, z, emb, tab, nfx, nfy, nfz, nxt);           \
            CONSUME(L)                                                             \
            cfx = nfx; cfy = nfy; cfz = nfz;                                       \
            _Pragma("unroll")                                                      \
            for (int c = 0; c < 8; c++) cur[c] = nxt[c];                           \
        }

        STEP(0)  STEP(1)  STEP(2)  STEP(3)
        STEP(4)  STEP(5)  STEP(6)  STEP(7)
        STEP(8)  STEP(9)  STEP(10) STEP(11)
        STEP(12) STEP(13) STEP(14)
        CONSUME(15)

        #undef STEP
        #undef CONSUME
    }

    __syncthreads();

    // Coalesced float4 writeback, evict-first so the 256MB output stream
    // doesn't flush the 57MB table out of L2.
    const int blockBase = blockIdx.x * (TPB * 32);
#pragma unroll
    for (int j = 0; j < 8; j++) {
        const int f4 = tid + j * TPB;
        const int fl = f4 * 4;
        const int p  = fl >> 5;
        const int k  = fl & 31;
        const int gp = blockIdx.x * TPB + p;
        if (gp < B) {
            const float4 v = *(const float4*)&s_out[p * PITCH + k];
            __stcs((float4*)&out[blockBase + fl], v);
        }
    }
}

extern "C" void kernel_launch(void* const* d_in, const int* in_sizes, int n_in,
                              void* d_out, int out_size)
{
    const float*  inp = (const float*)d_in[0];
    const float2* emb = (const float2*)d_in[1];
    const float2* tab = (const float2*)d_in[2];
    const int*    bnd = (n_in >= 4) ? (const int*)d_in[3] : nullptr;
    float* out = (float*)d_out;

    const int B = in_sizes[0] / 3;
    const int grid = (B + TPB - 1) / TPB;
    grid_encode_kernel<<<grid, TPB>>>(inp, emb, tab, bnd, out, B);
}

// round 11
// speedup vs baseline: 2.3328x; 1.0302x over previous
#include <cuda_runtime.h>
#include <cuda_bf16.h>
#include <cstdint>

#define PRIME1 2654435761u
#define PRIME2 805459861u
#define HMASK  0x7FFFFu

#define TPB 256
#define PITCH 36   // mult of 4 (aligned float4 reads); 8-thread LDS.128 phases conflict-free

// Issue all 8 corner gathers for one level. x-adjacent corner pairs are
// CONSECUTIVE table entries (dense: always; hashed: when ix even, since
// ix+1 = ix^1 and xor/mask preserve the LSB flip -> pair {2k,2k+1}).
// An even pair start is one 16B-aligned LDG.128: 1 wavefront + 1 sector
// instead of 2 each.
template<int LVL>
__device__ __forceinline__ void issue_level(
    float x, float y, float z,
    const float2* __restrict__ emb, const float2* __restrict__ tab,
    float& fx, float& fy, float& fz, float2* dst)
{
    const float scale = (float)(16 << LVL) - 1.0f;
    const float px = fmaf(x, scale, 0.5f);
    const float py = fmaf(y, scale, 0.5f);
    const float pz = fmaf(z, scale, 0.5f);
    const float fxf = floorf(px), fyf = floorf(py), fzf = floorf(pz);
    fx = px - fxf; fy = py - fyf; fz = pz - fzf;
    const unsigned ix = (unsigned)fxf, iy = (unsigned)fyf, iz = (unsigned)fzf;

    if (LVL <= 2) {
        const unsigned s  = (LVL == 0) ? 17u : (LVL == 1) ? 33u : 65u;
        const unsigned s2 = s * s;
        const unsigned off = (LVL == 2) ? 35944u : 0u;
        const float2* base = (LVL == 0) ? emb : tab;
        const unsigned id = ix + iy * s + iz * s2 + off;
        const unsigned starts[4] = {id, id + s, id + s2, id + s2 + s};
        #pragma unroll
        for (int p = 0; p < 4; p++) {
            const unsigned j = starts[p];
            if (!(j & 1u)) {
                const float4 v = __ldg((const float4*)(base + j));
                dst[2*p]   = make_float2(v.x, v.y);
                dst[2*p+1] = make_float2(v.z, v.w);
            } else {
                dst[2*p]   = __ldg(base + j);
                dst[2*p+1] = __ldg(base + j + 1);
            }
        }
    } else {
        const unsigned off = 310576u + (unsigned)(LVL - 3) * 524288u;
        const unsigned hy0 = iy * PRIME1, hy1 = hy0 + PRIME1;
        const unsigned hz0 = iz * PRIME2, hz1 = hz0 + PRIME2;
        const unsigned hh[4] = {hy0 ^ hz0, hy1 ^ hz0, hy0 ^ hz1, hy1 ^ hz1};
        if (!(ix & 1u)) {
            #pragma unroll
            for (int p = 0; p < 4; p++) {
                const unsigned j0 = (ix ^ hh[p]) & HMASK;
                const float4 v = __ldcg((const float4*)(tab + ((j0 & ~1u) + off)));
                const bool first = !(j0 & 1u);
                dst[2*p].x   = first ? v.x : v.z;
                dst[2*p].y   = first ? v.y : v.w;
                dst[2*p+1].x = first ? v.z : v.x;
                dst[2*p+1].y = first ? v.w : v.y;
            }
        } else {
            #pragma unroll
            for (int p = 0; p < 4; p++) {
                dst[2*p]   = __ldcg(tab + (((ix      ) ^ hh[p]) & HMASK) + off);
                dst[2*p+1] = __ldcg(tab + (((ix + 1u) ^ hh[p]) & HMASK) + off);
            }
        }
    }
}

__global__ void __launch_bounds__(TPB, 4)
grid_encode_kernel(const float* __restrict__ inp,
                   const float2* __restrict__ emb,    // level 0 (4920 rows)
                   const float2* __restrict__ tab,    // levels 1..15
                   const int* __restrict__ boundp,
                   float* __restrict__ out,
                   int B)
{
    __shared__ float s_out[TPB * PITCH];

    const int tid = threadIdx.x;
    const int b = blockIdx.x * TPB + tid;
    const bool valid = (b < B);

    float bnd = 1.0f;
    if (boundp) {
        int raw = __ldg(boundp);
        bnd = (raw > 0 && raw < 0x00800000) ? (float)raw : __int_as_float(raw);
    }
    const float inv = 0.5f / bnd;

    float x = 0.f, y = 0.f, z = 0.f;
    if (valid) {
        const float* p = inp + b * 3;
        x = __ldcs(p + 0); y = __ldcs(p + 1); z = __ldcs(p + 2);
    }
    x = fmaf(x, inv, 0.5f);
    y = fmaf(y, inv, 0.5f);
    z = fmaf(z, inv, 0.5f);

    if (valid) {
        // 3-stage software pipeline: levels l+1 AND l+2 are in flight while
        // level l is consumed -> ~24 loads outstanding per warp.
        float f0x, f0y, f0z, f1x, f1y, f1z;
        float2 cur0[8], cur1[8];
        issue_level<0>(x, y, z, emb, tab, f0x, f0y, f0z, cur0);
        issue_level<1>(x, y, z, emb, tab, f1x, f1y, f1z, cur1);

        #define CONSUME(L)                                                         \
        {                                                                          \
            const float gx = 1.0f - f0x, gy = 1.0f - f0y, gz = 1.0f - f0z;         \
            const float w00 = gx * gy, w10 = f0x * gy, w01 = gx * f0y, w11 = f0x * f0y; \
            const float wa = w00 * gz, wb = w10 * gz, wc = w01 * gz, wd = w11 * gz;\
            const float we = w00 * f0z, wf = w10 * f0z, wg = w01 * f0z, wh = w11 * f0z; \
            float r0 = wa * cur0[0].x,          r1 = wa * cur0[0].y;               \
            r0 = fmaf(wb, cur0[1].x, r0);       r1 = fmaf(wb, cur0[1].y, r1);      \
            r0 = fmaf(wc, cur0[2].x, r0);       r1 = fmaf(wc, cur0[2].y, r1);      \
            r0 = fmaf(wd, cur0[3].x, r0);       r1 = fmaf(wd, cur0[3].y, r1);      \
            r0 = fmaf(we, cur0[4].x, r0);       r1 = fmaf(we, cur0[4].y, r1);      \
            r0 = fmaf(wf, cur0[5].x, r0);       r1 = fmaf(wf, cur0[5].y, r1);      \
            r0 = fmaf(wg, cur0[6].x, r0);       r1 = fmaf(wg, cur0[6].y, r1);      \
            r0 = fmaf(wh, cur0[7].x, r0);       r1 = fmaf(wh, cur0[7].y, r1);      \
            *(float2*)&s_out[tid * PITCH + 2 * (L)] = make_float2(r0, r1);         \
        }

        #define SHIFT()                                                            \
        {                                                                          \
            f0x = f1x; f0y = f1y; f0z = f1z;                                       \
            f1x = n2x; f1y = n2y; f1z = n2z;                                       \
            _Pragma("unroll")                                                      \
            for (int c = 0; c < 8; c++) { cur0[c] = cur1[c]; cur1[c] = nxt2[c]; }  \
        }

        #define STEP(L)                                                            \
        {                                                                          \
            float n2x, n2y, n2z;                                                   \
            float2 nxt2[8];                                                        \
            issue_level<(L) + 2>(x, y, z, emb, tab, n2x, n2y, n2z, nxt2);          \
            CONSUME(L)                                                             \
            SHIFT()                                                                \
        }

        STEP(0)  STEP(1)  STEP(2)  STEP(3)
        STEP(4)  STEP(5)  STEP(6)  STEP(7)
        STEP(8)  STEP(9)  STEP(10) STEP(11)
        STEP(12) STEP(13)
        // two-stage drain
        CONSUME(14)
        {
            f0x = f1x; f0y = f1y; f0z = f1z;
            #pragma unroll
            for (int c = 0; c < 8; c++) cur0[c] = cur1[c];
        }
        CONSUME(15)

        #undef STEP
        #undef SHIFT
        #undef CONSUME
    }

    __syncthreads();

    // Coalesced float4 writeback, evict-first so the 256MB output stream
    // doesn't flush the 57MB table out of L2.
    const int blockBase = blockIdx.x * (TPB * 32);
#pragma unroll
    for (int j = 0; j < 8; j++) {
        const int f4 = tid + j * TPB;
        const int fl = f4 * 4;
        const int p  = fl >> 5;
        const int k  = fl & 31;
        const int gp = blockIdx.x * TPB + p;
        if (gp < B) {
            const float4 v = *(const float4*)&s_out[p * PITCH + k];
            __stcs((float4*)&out[blockBase + fl], v);
        }
    }
}

extern "C" void kernel_launch(void* const* d_in, const int* in_sizes, int n_in,
                              void* d_out, int out_size)
{
    const float*  inp = (const float*)d_in[0];
    const float2* emb = (const float2*)d_in[1];
    const float2* tab = (const float2*)d_in[2];
    const int*    bnd = (n_in >= 4) ? (const int*)d_in[3] : nullptr;
    float* out = (float*)d_out;

    const int B = in_sizes[0] / 3;
    const int grid = (B + TPB - 1) / TPB;
    grid_encode_kernel<<<grid, TPB>>>(inp, emb, tab, bnd, out, B);
}

// round 12
// speedup vs baseline: 2.4129x; 1.0344x over previous
#include <cuda_runtime.h>
#include <cuda_bf16.h>
#include <cstdint>

#define PRIME1 2654435761u
#define PRIME2 805459861u
#define HMASK  0x7FFFFu

#define TPB 256
#define PITCH 36   // mult of 4 (aligned float4 reads); 8-thread LDS.128 phases conflict-free

// Paired dense table: g_d2[j] = (full[j], full[j+1]) for the 3 dense levels
// (global rows [0, 315496)). Makes EVERY dense x-pair one 16B-aligned LDG.128
// regardless of parity (dense pair indices are always consecutive).
#define D2_TOTAL 315496
__device__ float4 g_d2[D2_TOTAL];

__global__ void __launch_bounds__(256)
build_dense_pairs(const float2* __restrict__ emb, const float2* __restrict__ tab)
{
    const int j = blockIdx.x * 256 + threadIdx.x;
    if (j >= D2_TOTAL) return;
    float2 a, b;
    if (j < 4920) {                       // level 0 lives in `embeddings`
        a = emb[j];
        b = (j + 1 < 4920) ? emb[j + 1] : make_float2(0.f, 0.f);
    } else {                              // levels 1,2 live in `table`
        const int t = j - 4920;
        a = tab[t];
        b = (j + 1 < D2_TOTAL) ? tab[t + 1] : make_float2(0.f, 0.f);
    }
    g_d2[j] = make_float4(a.x, a.y, b.x, b.y);
}

// Issue all 8 corner gathers for one level.
// Dense: 4 LDG.128 from the paired table (no parity branch).
// Hashed: x-pairs are {2k,2k+1} iff ix even (ix+1 = ix^1 and xor/mask keep the
// LSB flip) -> one LDG.128; odd ix needs 2 independent LDG.64.
template<int LVL>
__device__ __forceinline__ void issue_level(
    float x, float y, float z,
    const float2* __restrict__ tab,
    float& fx, float& fy, float& fz, float2* dst)
{
    const float scale = (float)(16 << LVL) - 1.0f;
    const float px = fmaf(x, scale, 0.5f);
    const float py = fmaf(y, scale, 0.5f);
    const float pz = fmaf(z, scale, 0.5f);
    const float fxf = floorf(px), fyf = floorf(py), fzf = floorf(pz);
    fx = px - fxf; fy = py - fyf; fz = pz - fzf;
    const unsigned ix = (unsigned)fxf, iy = (unsigned)fyf, iz = (unsigned)fzf;

    if (LVL <= 2) {
        const unsigned s  = (LVL == 0) ? 17u : (LVL == 1) ? 33u : 65u;
        const unsigned s2 = s * s;
        const unsigned gb = (LVL == 0) ? 0u : (LVL == 1) ? 4920u : 40864u;
        const unsigned id = gb + ix + iy * s + iz * s2;
        const unsigned starts[4] = {id, id + s, id + s2, id + s2 + s};
        #pragma unroll
        for (int p = 0; p < 4; p++) {
            const float4 v = __ldg(&g_d2[starts[p]]);
            dst[2*p]   = make_float2(v.x, v.y);
            dst[2*p+1] = make_float2(v.z, v.w);
        }
    } else {
        const unsigned off = 310576u + (unsigned)(LVL - 3) * 524288u;
        const unsigned hy0 = iy * PRIME1, hy1 = hy0 + PRIME1;
        const unsigned hz0 = iz * PRIME2, hz1 = hz0 + PRIME2;
        const unsigned hh[4] = {hy0 ^ hz0, hy1 ^ hz0, hy0 ^ hz1, hy1 ^ hz1};
        if (!(ix & 1u)) {
            #pragma unroll
            for (int p = 0; p < 4; p++) {
                const unsigned j0 = (ix ^ hh[p]) & HMASK;
                const float4 v = __ldcg((const float4*)(tab + ((j0 & ~1u) + off)));
                const bool first = !(j0 & 1u);
                dst[2*p].x   = first ? v.x : v.z;
                dst[2*p].y   = first ? v.y : v.w;
                dst[2*p+1].x = first ? v.z : v.x;
                dst[2*p+1].y = first ? v.w : v.y;
            }
        } else {
            #pragma unroll
            for (int p = 0; p < 4; p++) {
                dst[2*p]   = __ldcg(tab + (((ix      ) ^ hh[p]) & HMASK) + off);
                dst[2*p+1] = __ldcg(tab + (((ix + 1u) ^ hh[p]) & HMASK) + off);
            }
        }
    }
}

__global__ void __launch_bounds__(TPB, 5)
grid_encode_kernel(const float* __restrict__ inp,
                   const float2* __restrict__ tab,    // levels 1..15
                   const int* __restrict__ boundp,
                   float* __restrict__ out,
                   int B)
{
    __shared__ float s_out[TPB * PITCH];

    const int tid = threadIdx.x;
    const int b = blockIdx.x * TPB + tid;
    const bool valid = (b < B);

    float bnd = 1.0f;
    if (boundp) {
        int raw = __ldg(boundp);
        bnd = (raw > 0 && raw < 0x00800000) ? (float)raw : __int_as_float(raw);
    }
    const float inv = 0.5f / bnd;

    float x = 0.f, y = 0.f, z = 0.f;
    if (valid) {
        const float* p = inp + b * 3;
        x = __ldcs(p + 0); y = __ldcs(p + 1); z = __ldcs(p + 2);
    }
    x = fmaf(x, inv, 0.5f);
    y = fmaf(y, inv, 0.5f);
    z = fmaf(z, inv, 0.5f);

    if (valid) {
        // 2-stage software pipeline: level l+1's gathers issued before level
        // l's results are consumed -> ~16 loads in flight per warp.
        float cfx, cfy, cfz;
        float2 cur[8];
        issue_level<0>(x, y, z, tab, cfx, cfy, cfz, cur);

        #define CONSUME(L)                                                         \
        {                                                                          \
            const float gx = 1.0f - cfx, gy = 1.0f - cfy, gz = 1.0f - cfz;         \
            const float w00 = gx * gy, w10 = cfx * gy, w01 = gx * cfy, w11 = cfx * cfy; \
            const float wa = w00 * gz, wb = w10 * gz, wc = w01 * gz, wd = w11 * gz;\
            const float we = w00 * cfz, wf = w10 * cfz, wg = w01 * cfz, wh = w11 * cfz; \
            float r0 = wa * cur[0].x,          r1 = wa * cur[0].y;                 \
            r0 = fmaf(wb, cur[1].x, r0);       r1 = fmaf(wb, cur[1].y, r1);        \
            r0 = fmaf(wc, cur[2].x, r0);       r1 = fmaf(wc, cur[2].y, r1);        \
            r0 = fmaf(wd, cur[3].x, r0);       r1 = fmaf(wd, cur[3].y, r1);        \
            r0 = fmaf(we, cur[4].x, r0);       r1 = fmaf(we, cur[4].y, r1);        \
            r0 = fmaf(wf, cur[5].x, r0);       r1 = fmaf(wf, cur[5].y, r1);        \
            r0 = fmaf(wg, cur[6].x, r0);       r1 = fmaf(wg, cur[6].y, r1);        \
            r0 = fmaf(wh, cur[7].x, r0);       r1 = fmaf(wh, cur[7].y, r1);        \
            *(float2*)&s_out[tid * PITCH + 2 * (L)] = make_float2(r0, r1);         \
        }

        #define STEP(L)                                                            \
        {                                                                          \
            float nfx, nfy, nfz;                                                   \
            float2 nxt[8];                                                         \
            issue_level<(L) + 1>(x, y, z, tab, nfx, nfy, nfz, nxt);                \
            CONSUME(L)                                                             \
            cfx = nfx; cfy = nfy; cfz = nfz;                                       \
            _Pragma("unroll")                                                      \
            for (int c = 0; c < 8; c++) cur[c] = nxt[c];                           \
        }

        STEP(0)  STEP(1)  STEP(2)  STEP(3)
        STEP(4)  STEP(5)  STEP(6)  STEP(7)
        STEP(8)  STEP(9)  STEP(10) STEP(11)
        STEP(12) STEP(13) STEP(14)
        CONSUME(15)

        #undef STEP
        #undef CONSUME
    }

    __syncthreads();

    // Coalesced float4 writeback, evict-first so the 256MB output stream
    // doesn't flush the 57MB table out of L2.
    const int blockBase = blockIdx.x * (TPB * 32);
#pragma unroll
    for (int j = 0; j < 8; j++) {
        const int f4 = tid + j * TPB;
        const int fl = f4 * 4;
        const int p  = fl >> 5;
        const int k  = fl & 31;
        const int gp = blockIdx.x * TPB + p;
        if (gp < B) {
            const float4 v = *(const float4*)&s_out[p * PITCH + k];
            __stcs((float4*)&out[blockBase + fl], v);
        }
    }
}

extern "C" void kernel_launch(void* const* d_in, const int* in_sizes, int n_in,
                              void* d_out, int out_size)
{
    const float*  inp = (const float*)d_in[0];
    const float2* emb = (const float2*)d_in[1];
    const float2* tab = (const float2*)d_in[2];
    const int*    bnd = (n_in >= 4) ? (const int*)d_in[3] : nullptr;
    float* out = (float*)d_out;

    const int B = in_sizes[0] / 3;

    // Build the paired dense table (same stream -> ordered before main kernel).
    build_dense_pairs<<<(D2_TOTAL + 255) / 256, 256>>>(emb, tab);

    const int grid = (B + TPB - 1) / TPB;
    grid_encode_kernel<<<grid, TPB>>>(inp, tab, bnd, out, B);
}

// round 13
// speedup vs baseline: 2.4976x; 1.0351x over previous
#include <cuda_runtime.h>
#include <cuda_bf16.h>
#include <cstdint>

#define PRIME1 2654435761u
#define PRIME2 805459861u
#define HMASK  0x7FFFFu

#define TPB 256
#define PITCH 36   // mult of 4 (aligned float4 reads); 8-thread LDS.128 phases conflict-free

// Paired dense table: g_d2[j] = (full[j], full[j+1]) for the 3 dense levels
// (global rows [0, 315496)). Makes EVERY dense x-pair one 16B-aligned LDG.128
// regardless of parity (dense pair indices are always consecutive).
#define D2_TOTAL 315496
__device__ float4 g_d2[D2_TOTAL];

__global__ void __launch_bounds__(256)
build_dense_pairs(const float2* __restrict__ emb, const float2* __restrict__ tab)
{
    const int j = blockIdx.x * 256 + threadIdx.x;
    if (j >= D2_TOTAL) return;
    float2 a, b;
    if (j < 4920) {                       // level 0 lives in `embeddings`
        a = emb[j];
        b = (j + 1 < 4920) ? emb[j + 1] : make_float2(0.f, 0.f);
    } else {                              // levels 1,2 live in `table`
        const int t = j - 4920;
        a = tab[t];
        b = (j + 1 < D2_TOTAL) ? tab[t + 1] : make_float2(0.f, 0.f);
    }
    g_d2[j] = make_float4(a.x, a.y, b.x, b.y);
}

// Issue all 8 corner gathers for one level.
// Dense: 4 LDG.128 from the paired table (no parity branch). Levels 0-1 use
// .ca (small, real L1 reuse); level 2 uses .cg (4.3MB paired region, ~0% L1
// hit -> don't let it thrash the L1 lines of levels 0-1).
// Hashed: x-pairs are {2k,2k+1} iff ix even (ix+1 = ix^1 and xor/mask keep the
// LSB flip) -> one LDG.128; odd ix needs 2 independent LDG.64. All .cg.
template<int LVL>
__device__ __forceinline__ void issue_level(
    float x, float y, float z,
    const float2* __restrict__ tab,
    float& fx, float& fy, float& fz, float2* dst)
{
    const float scale = (float)(16 << LVL) - 1.0f;
    const float px = fmaf(x, scale, 0.5f);
    const float py = fmaf(y, scale, 0.5f);
    const float pz = fmaf(z, scale, 0.5f);
    const float fxf = floorf(px), fyf = floorf(py), fzf = floorf(pz);
    fx = px - fxf; fy = py - fyf; fz = pz - fzf;
    const unsigned ix = (unsigned)fxf, iy = (unsigned)fyf, iz = (unsigned)fzf;

    if (LVL <= 2) {
        const unsigned s  = (LVL == 0) ? 17u : (LVL == 1) ? 33u : 65u;
        const unsigned s2 = s * s;
        const unsigned gb = (LVL == 0) ? 0u : (LVL == 1) ? 4920u : 40864u;
        const unsigned id = gb + ix + iy * s + iz * s2;
        const unsigned starts[4] = {id, id + s, id + s2, id + s2 + s};
        #pragma unroll
        for (int p = 0; p < 4; p++) {
            const float4 v = (LVL == 2) ? __ldcg(&g_d2[starts[p]])
                                        : __ldg(&g_d2[starts[p]]);
            dst[2*p]   = make_float2(v.x, v.y);
            dst[2*p+1] = make_float2(v.z, v.w);
        }
    } else {
        const unsigned off = 310576u + (unsigned)(LVL - 3) * 524288u;
        const unsigned hy0 = iy * PRIME1, hy1 = hy0 + PRIME1;
        const unsigned hz0 = iz * PRIME2, hz1 = hz0 + PRIME2;
        const unsigned hh[4] = {hy0 ^ hz0, hy1 ^ hz0, hy0 ^ hz1, hy1 ^ hz1};
        if (!(ix & 1u)) {
            #pragma unroll
            for (int p = 0; p < 4; p++) {
                const unsigned j0 = (ix ^ hh[p]) & HMASK;
                const float4 v = __ldcg((const float4*)(tab + ((j0 & ~1u) + off)));
                const bool first = !(j0 & 1u);
                dst[2*p].x   = first ? v.x : v.z;
                dst[2*p].y   = first ? v.y : v.w;
                dst[2*p+1].x = first ? v.z : v.x;
                dst[2*p+1].y = first ? v.w : v.y;
            }
        } else {
            #pragma unroll
            for (int p = 0; p < 4; p++) {
                dst[2*p]   = __ldcg(tab + (((ix      ) ^ hh[p]) & HMASK) + off);
                dst[2*p+1] = __ldcg(tab + (((ix + 1u) ^ hh[p]) & HMASK) + off);
            }
        }
    }
}

__global__ void __launch_bounds__(TPB, 5)
grid_encode_kernel(const float* __restrict__ inp,
                   const float2* __restrict__ tab,    // levels 1..15
                   const int* __restrict__ boundp,
                   float* __restrict__ out,
                   int B)
{
    __shared__ float s_out[TPB * PITCH];

    const int tid = threadIdx.x;
    const int b = blockIdx.x * TPB + tid;
    const bool valid = (b < B);

    float bnd = 1.0f;
    if (boundp) {
        int raw = __ldg(boundp);
        bnd = (raw > 0 && raw < 0x00800000) ? (float)raw : __int_as_float(raw);
    }
    const float inv = 0.5f / bnd;

    float x = 0.f, y = 0.f, z = 0.f;
    if (valid) {
        const float* p = inp + b * 3;
        x = __ldcs(p + 0); y = __ldcs(p + 1); z = __ldcs(p + 2);
    }
    x = fmaf(x, inv, 0.5f);
    y = fmaf(y, inv, 0.5f);
    z = fmaf(z, inv, 0.5f);

    if (valid) {
        // 2-stage software pipeline: level l+1's gathers issued before level
        // l's results are consumed -> ~16 loads in flight per warp.
        float cfx, cfy, cfz;
        float2 cur[8];
        issue_level<0>(x, y, z, tab, cfx, cfy, cfz, cur);

        #define CONSUME(L)                                                         \
        {                                                                          \
            const float gx = 1.0f - cfx, gy = 1.0f - cfy, gz = 1.0f - cfz;         \
            const float w00 = gx * gy, w10 = cfx * gy, w01 = gx * cfy, w11 = cfx * cfy; \
            const float wa = w00 * gz, wb = w10 * gz, wc = w01 * gz, wd = w11 * gz;\
            const float we = w00 * cfz, wf = w10 * cfz, wg = w01 * cfz, wh = w11 * cfz; \
            float r0 = wa * cur[0].x,          r1 = wa * cur[0].y;                 \
            r0 = fmaf(wb, cur[1].x, r0);       r1 = fmaf(wb, cur[1].y, r1);        \
            r0 = fmaf(wc, cur[2].x, r0);       r1 = fmaf(wc, cur[2].y, r1);        \
            r0 = fmaf(wd, cur[3].x, r0);       r1 = fmaf(wd, cur[3].y, r1);        \
            r0 = fmaf(we, cur[4].x, r0);       r1 = fmaf(we, cur[4].y, r1);        \
            r0 = fmaf(wf, cur[5].x, r0);       r1 = fmaf(wf, cur[5].y, r1);        \
            r0 = fmaf(wg, cur[6].x, r0);       r1 = fmaf(wg, cur[6].y, r1);        \
            r0 = fmaf(wh, cur[7].x, r0);       r1 = fmaf(wh, cur[7].y, r1);        \
            *(float2*)&s_out[tid * PITCH + 2 * (L)] = make_float2(r0, r1);         \
        }

        #define STEP(L)                                                            \
        {                                                                          \
            float nfx, nfy, nfz;                                                   \
            float2 nxt[8];                                                         \
            issue_level<(L) + 1>(x, y, z, tab, nfx, nfy, nfz, nxt);                \
            CONSUME(L)                                                             \
            cfx = nfx; cfy = nfy; cfz = nfz;                                       \
            _Pragma("unroll")                                                      \
            for (int c = 0; c < 8; c++) cur[c] = nxt[c];                           \
        }

        STEP(0)  STEP(1)  STEP(2)  STEP(3)
        STEP(4)  STEP(5)  STEP(6)  STEP(7)
        STEP(8)  STEP(9)  STEP(10) STEP(11)
        STEP(12) STEP(13) STEP(14)
        CONSUME(15)

        #undef STEP
        #undef CONSUME
    }

    __syncthreads();

    // Coalesced float4 writeback, evict-first so the 256MB output stream
    // doesn't flush the 57MB table out of L2.
    const int blockBase = blockIdx.x * (TPB * 32);
#pragma unroll
    for (int j = 0; j < 8; j++) {
        const int f4 = tid + j * TPB;
        const int fl = f4 * 4;
        const int p  = fl >> 5;
        const int k  = fl & 31;
        const int gp = blockIdx.x * TPB + p;
        if (gp < B) {
            const float4 v = *(const float4*)&s_out[p * PITCH + k];
            __stcs((float4*)&out[blockBase + fl], v);
        }
    }
}

extern "C" void kernel_launch(void* const* d_in, const int* in_sizes, int n_in,
                              void* d_out, int out_size)
{
    const float*  inp = (const float*)d_in[0];
    const float2* emb = (const float2*)d_in[1];
    const float2* tab = (const float2*)d_in[2];
    const int*    bnd = (n_in >= 4) ? (const int*)d_in[3] : nullptr;
    float* out = (float*)d_out;

    const int B = in_sizes[0] / 3;

    // Build the paired dense table (same stream -> ordered before main kernel).
    build_dense_pairs<<<(D2_TOTAL + 255) / 256, 256>>>(emb, tab);

    const int grid = (B + TPB - 1) / TPB;
    grid_encode_kernel<<<grid, TPB>>>(inp, tab, bnd, out, B);
}